// round 5
// baseline (speedup 1.0000x reference)
#include <cuda_runtime.h>
#include <math.h>

#define HH   256
#define LL   5
#define TT   1000
#define BB   128

typedef unsigned long long ull;

// Cross-layer mailboxes: one 8-byte {tag=t+1, value} slot per (layer, batch, t).
// Written exactly once per launch; tags zeroed by reset kernel each launch.
__device__ ull   g_mbox[LL - 1][BB][TT];   // 4.096 MB
__device__ float g_hseq[BB][TT];           // layer-4 outputs, 512 KB

__device__ __forceinline__ float tanhapx(float x) {
    float r;
    asm("tanh.approx.f32 %0, %1;" : "=f"(r) : "f"(x));
    return r;
}

__device__ __forceinline__ int redux_s32(int v) {
    int r;
    asm volatile("redux.sync.add.s32 %0, %1, 0xffffffff;" : "=r"(r) : "r"(v));
    return r;
}

// ---------------------------------------------------------------- reset
__global__ void reset_mbox_kernel() {
    ull* p = &g_mbox[0][0][0];
    const int n = (LL - 1) * BB * TT;
    for (int i = blockIdx.x * blockDim.x + threadIdx.x; i < n;
         i += gridDim.x * blockDim.x)
        p[i] = 0ull;
}

// ---------------------------------------------------------------- LSTM pipeline
// grid = LL*BB single-warp blocks; block (l, b) runs layer l of batch b.
// Each of the 32 lanes owns 8 hidden channels: h = lane + 32*ch.
__global__ void __launch_bounds__(32)
lstm_layer_kernel(const float* __restrict__ x,
                  const float* __restrict__ Wih,
                  const float* __restrict__ Whh,
                  const float* __restrict__ bih,
                  const float* __restrict__ bhh,
                  const float* __restrict__ Whr)
{
    __shared__ __align__(16) float xbuf[TT];

    const int lane = threadIdx.x;
    const int l    = blockIdx.x >> 7;      // layer
    const int b    = blockIdx.x & 127;     // batch element

    // ---- per-thread weights: 8 channels x 4 gates ----
    // gate order i,f,g,o; sigmoid(x)=0.5*tanh(0.5x)+0.5 with 0.5 folded in.
    float wI[8][4], wH[8][4], bS[8][4], wR[8];
#pragma unroll
    for (int ch = 0; ch < 8; ++ch) {
        int h = lane + ch * 32;
#pragma unroll
        for (int g = 0; g < 4; ++g) {
            int idx = l * 1024 + g * 256 + h;
            float s = (g == 2) ? 1.0f : 0.5f;
            wI[ch][g] = Wih[idx] * s;
            wH[ch][g] = Whh[idx] * s;
            bS[ch][g] = (bih[idx] + bhh[idx]) * s;
        }
        wR[ch] = Whr[l * 256 + h];
    }

    if (l == 0) {
        for (int k = lane; k < TT; k += 32)
            xbuf[k] = x[b * TT + k];
    }
    __syncwarp();

    const ull* mb_in  = (l > 0) ? g_mbox[l - 1][b] : (const ull*)0;
    ull*       mb_out = (l < LL - 1) ? g_mbox[l][b] : (ull*)0;

    float c[8];
#pragma unroll
    for (int ch = 0; ch < 8; ++ch) c[ch] = 0.0f;
    float hp = 0.0f;
    ull pre = 0ull;
    if (l > 0) pre = *(volatile const ull*)mb_in;   // prefetch slot 0

    for (int t = 0; t < TT; ++t) {
        // ---- obtain input (register-resident in steady state) ----
        float in;
        if (l == 0) {
            in = xbuf[t];
        } else {
            ull v = pre;
            const unsigned want = (unsigned)(t + 1);
            while ((unsigned)(v >> 32) != want)
                v = *(volatile const ull*)(mb_in + t);
            in = __uint_as_float((unsigned)v);
            if (t + 1 < TT)                          // prefetch next slot;
                pre = *(volatile const ull*)(mb_in + t + 1);  // overlaps compute
        }

        // ---- 8 channels of the LSTM cell (f32) ----
        float acc = 0.0f;
#pragma unroll
        for (int ch = 0; ch < 8; ++ch) {
            float gi = fmaf(in, wI[ch][0], fmaf(hp, wH[ch][0], bS[ch][0]));
            float gf = fmaf(in, wI[ch][1], fmaf(hp, wH[ch][1], bS[ch][1]));
            float gg = fmaf(in, wI[ch][2], fmaf(hp, wH[ch][2], bS[ch][2]));
            float go = fmaf(in, wI[ch][3], fmaf(hp, wH[ch][3], bS[ch][3]));
            float i_ = fmaf(tanhapx(gi), 0.5f, 0.5f);
            float f_ = fmaf(tanhapx(gf), 0.5f, 0.5f);
            float g_ = tanhapx(gg);
            float o_ = fmaf(tanhapx(go), 0.5f, 0.5f);
            c[ch] = fmaf(f_, c[ch], i_ * g_);
            acc = fmaf(o_ * tanhapx(c[ch]), wR[ch], acc);
        }

        // ---- reduce 256 channels in one warp-wide fixed-point redux ----
        int q = __float2int_rn(acc * 16777216.0f);          // 2^24
        int r = redux_s32(q);                               // full sum, all lanes
        hp = (float)r * 5.9604644775390625e-8f;             // 2^-24

        // ---- publish ----
        if (lane == 0) {
            if (mb_out) {
                ull v = ((ull)(unsigned)(t + 1) << 32) |
                        (ull)__float_as_uint(hp);
                *(volatile ull*)(mb_out + t) = v;
            } else {
                g_hseq[b][t] = hp;
            }
        }
    }
}

// ---------------------------------------------------------------- MLP head
__global__ void __launch_bounds__(128)
mlp_kernel(const float* __restrict__ W1, const float* __restrict__ b1,
           const float* __restrict__ W2, const float* __restrict__ b2,
           const float* __restrict__ W3, const float* __restrict__ b3,
           const float* __restrict__ W4, const float* __restrict__ b4,
           float* __restrict__ out)
{
    __shared__ __align__(16) float hbuf[TT];
    __shared__ float a1[100], a2[100], a3[100];

    const int tid = threadIdx.x;
    const int b   = blockIdx.x;

    for (int k = tid; k < TT; k += 128)
        hbuf[k] = g_hseq[b][k];
    __syncthreads();

    if (tid < 100) {
        const float* wrow = W1 + tid * 1000;
        float acc0 = 0.f, acc1 = 0.f, acc2 = 0.f, acc3 = 0.f;
#pragma unroll 2
        for (int k = 0; k < 1000; k += 4) {
            float4 wv = *(const float4*)(wrow + k);
            float4 hv = *(const float4*)(hbuf + k);
            acc0 = fmaf(wv.x, hv.x, acc0);
            acc1 = fmaf(wv.y, hv.y, acc1);
            acc2 = fmaf(wv.z, hv.z, acc2);
            acc3 = fmaf(wv.w, hv.w, acc3);
        }
        float acc = ((acc0 + acc1) + (acc2 + acc3)) + b1[tid];
        a1[tid] = 1.0f / (1.0f + expf(-acc));
    }
    __syncthreads();
    if (tid < 100) {
        const float* wrow = W2 + tid * 100;
        float acc = b2[tid];
#pragma unroll 4
        for (int k = 0; k < 100; ++k)
            acc = fmaf(wrow[k], a1[k], acc);
        a2[tid] = 1.0f / (1.0f + expf(-acc));
    }
    __syncthreads();
    if (tid < 100) {
        const float* wrow = W3 + tid * 100;
        float acc = b3[tid];
#pragma unroll 4
        for (int k = 0; k < 100; ++k)
            acc = fmaf(wrow[k], a2[k], acc);
        a3[tid] = fmaxf(acc, 0.0f);
    }
    __syncthreads();
    if (tid == 0) {
        float acc = b4[0];
#pragma unroll 4
        for (int k = 0; k < 100; ++k)
            acc = fmaf(W4[k], a3[k], acc);
        out[b] = acc;
    }
}

extern "C" void kernel_launch(void* const* d_in, const int* in_sizes, int n_in,
                              void* d_out, int out_size)
{
    const float* x   = (const float*)d_in[0];
    const float* Wih = (const float*)d_in[1];
    const float* Whh = (const float*)d_in[2];
    const float* bih = (const float*)d_in[3];
    const float* bhh = (const float*)d_in[4];
    const float* Whr = (const float*)d_in[5];
    const float* W1  = (const float*)d_in[6];
    const float* b1  = (const float*)d_in[7];
    const float* W2  = (const float*)d_in[8];
    const float* b2  = (const float*)d_in[9];
    const float* W3  = (const float*)d_in[10];
    const float* b3  = (const float*)d_in[11];
    const float* W4  = (const float*)d_in[12];
    const float* b4  = (const float*)d_in[13];
    float* out = (float*)d_out;

    reset_mbox_kernel<<<256, 256>>>();
    lstm_layer_kernel<<<LL * BB, 32>>>(x, Wih, Whh, bih, bhh, Whr);
    mlp_kernel<<<BB, 128>>>(W1, b1, W2, b2, W3, b3, W4, b4, out);
}